// round 1
// baseline (speedup 1.0000x reference)
#include <cuda_runtime.h>
#include <cuda_bf16.h>

// Problem constants
#define NWIN   1024           // 16 batches * 8 * 8 windows
#define MTOT   65536          // NWIN * 64 tokens
#define CDIM   512
#define NHEAD  16
#define HDIM   32

// Scratch (device globals — no allocation allowed)
__device__ float g_xw [ (size_t)MTOT * CDIM ];        // gathered/scrambled windows (M x 512)
__device__ float g_qkv[ (size_t)3 * MTOT * CDIM ];    // [s][w][h][t][d]
__device__ float g_xo [ (size_t)MTOT * CDIM ];        // attention out, [w][t][C]

// ---------------------------------------------------------------------------
// 1) Gather: xw[w, t, cc] = x[b, n(i,j), c]
//    c = (t&7)*64 + (t>>3)*8 + cc/64 ; i = (cc>>3)&7 ; j = cc&7
//    The 8 values cc64 + 64*r (r=0..7) share (i,j) and have consecutive c,
//    so each thread reads 8 contiguous floats (32B) and scatters 8 writes.
// ---------------------------------------------------------------------------
__global__ __launch_bounds__(256) void gather_kernel(const float* __restrict__ x) {
    int idx = blockIdx.x * blockDim.x + threadIdx.x;      // [0, NWIN*64*64)
    int cc64 = idx & 63;
    int t    = (idx >> 6) & 63;
    int w    = idx >> 12;
    int b  = w >> 6;
    int wh = (w >> 3) & 7;
    int ww = w & 7;
    int i = cc64 >> 3;
    int j = cc64 & 7;
    int base_c = (t & 7) * 64 + (t >> 3) * 8;             // multiple of 8
    int n = (wh * 8 + i) * 64 + (ww * 8 + j);
    const float* src = x + ((size_t)(b * 4096 + n)) * 512 + base_c;
    float4 v0 = *(const float4*)(src);
    float4 v1 = *(const float4*)(src + 4);
    float* dst = g_xw + (size_t)w * 32768 + t * 512 + cc64;
    dst[0]   = v0.x; dst[64]  = v0.y; dst[128] = v0.z; dst[192] = v0.w;
    dst[256] = v1.x; dst[320] = v1.y; dst[384] = v1.z; dst[448] = v1.w;
}

// ---------------------------------------------------------------------------
// SGEMM tile config: C[m,n] = sum_k A[m,k] * W[n,k]   (A: MTOTx512, W: Nx512)
// ---------------------------------------------------------------------------
#define BM 128
#define BN 64
#define BK 16

// 2) QKV GEMM: A = g_xw, W = w_qkv (1536x512). Scatter to g_qkv[s][w][h][t][d].
__global__ __launch_bounds__(256) void qkv_gemm_kernel(const float* __restrict__ Wmat) {
    __shared__ float As[BK][BM];
    __shared__ float Bs[BK][BN];
    const int tid = threadIdx.x;
    const int m0 = blockIdx.x * BM;
    const int n0 = blockIdx.y * BN;
    const int tx = tid & 15;       // n direction (4 each)
    const int ty = tid >> 4;       // m direction (8 each)

    float acc[8][4];
#pragma unroll
    for (int i = 0; i < 8; i++)
#pragma unroll
        for (int j = 0; j < 4; j++) acc[i][j] = 0.f;

    const int la0 = tid * 2;           // A: 2 float4 per thread (128x16)
    const int bn  = tid >> 2;          // B: 1 float4 per thread (64x16)
    const int bk  = (tid & 3) * 4;

    for (int kb = 0; kb < 512; kb += BK) {
#pragma unroll
        for (int v = 0; v < 2; v++) {
            int la = la0 + v;
            int m  = la >> 2;
            int kq = (la & 3) * 4;
            float4 av = *(const float4*)(g_xw + (size_t)(m0 + m) * 512 + kb + kq);
            As[kq+0][m] = av.x; As[kq+1][m] = av.y;
            As[kq+2][m] = av.z; As[kq+3][m] = av.w;
        }
        {
            float4 bv = *(const float4*)(Wmat + (size_t)(n0 + bn) * 512 + kb + bk);
            Bs[bk+0][bn] = bv.x; Bs[bk+1][bn] = bv.y;
            Bs[bk+2][bn] = bv.z; Bs[bk+3][bn] = bv.w;
        }
        __syncthreads();
#pragma unroll
        for (int k = 0; k < BK; k++) {
            float a[8], b[4];
            float4 a0 = *(const float4*)&As[k][ty * 8];
            float4 a1 = *(const float4*)&As[k][ty * 8 + 4];
            a[0]=a0.x; a[1]=a0.y; a[2]=a0.z; a[3]=a0.w;
            a[4]=a1.x; a[5]=a1.y; a[6]=a1.z; a[7]=a1.w;
            float4 b0 = *(const float4*)&Bs[k][tx * 4];
            b[0]=b0.x; b[1]=b0.y; b[2]=b0.z; b[3]=b0.w;
#pragma unroll
            for (int i = 0; i < 8; i++)
#pragma unroll
                for (int j = 0; j < 4; j++) acc[i][j] += a[i] * b[j];
        }
        __syncthreads();
    }

    // Epilogue: n = s*512 + h*32 + d ; store to g_qkv[s][w][h][t][d]
    const int n = n0 + tx * 4;
    const int s = n >> 9;
    const int h = (n >> 5) & 15;
    const int d = n & 31;
#pragma unroll
    for (int i = 0; i < 8; i++) {
        int m = m0 + ty * 8 + i;
        int w = m >> 6, t = m & 63;
        float* dst = g_qkv + (((size_t)s * NWIN + w) * 16 + h) * 2048 + t * 32 + d;
        *(float4*)dst = make_float4(acc[i][0], acc[i][1], acc[i][2], acc[i][3]);
    }
}

// ---------------------------------------------------------------------------
// 3) Attention: one block per (window, head); 64 threads (one per query row)
// ---------------------------------------------------------------------------
__global__ __launch_bounds__(64) void attn_kernel() {
    __shared__ float Qs[64 * 33];   // padded stride 33 -> conflict-free row reads
    __shared__ float Ks[64 * 32];
    __shared__ float Vs[64 * 32];
    const int w = blockIdx.x >> 4;
    const int h = blockIdx.x & 15;
    const size_t base = ((size_t)w * 16 + h) * 2048;
    const float* qb = g_qkv + base;
    const float* kb = g_qkv + (size_t)MTOT * 512 + base;
    const float* vb = g_qkv + (size_t)2 * MTOT * 512 + base;
    const int t = threadIdx.x;

#pragma unroll
    for (int v = 0; v < 8; v++) {
        int idx = v * 64 + t;                       // float4 index in [0,512)
        ((float4*)Ks)[idx] = ((const float4*)kb)[idx];
        ((float4*)Vs)[idx] = ((const float4*)vb)[idx];
        float4 qv = ((const float4*)qb)[idx];
        int row = idx >> 3;
        int d0  = (idx & 7) * 4;
        Qs[row * 33 + d0 + 0] = qv.x;
        Qs[row * 33 + d0 + 1] = qv.y;
        Qs[row * 33 + d0 + 2] = qv.z;
        Qs[row * 33 + d0 + 3] = qv.w;
    }
    __syncthreads();

    const float* qrow = Qs + t * 33;
    float s[64];
    float mx = -1e30f;
#pragma unroll
    for (int tt = 0; tt < 64; tt++) {
        float dot = 0.f;
#pragma unroll
        for (int d = 0; d < 32; d++) dot += qrow[d] * Ks[tt * 32 + d];
        dot *= 0.17677669529663687f;     // 1/sqrt(32)
        s[tt] = dot;
        mx = fmaxf(mx, dot);
    }
    float sum = 0.f;
#pragma unroll
    for (int tt = 0; tt < 64; tt++) {
        float e = __expf(s[tt] - mx);
        s[tt] = e;
        sum += e;
    }
    float o[32];
#pragma unroll
    for (int d = 0; d < 32; d++) o[d] = 0.f;
#pragma unroll
    for (int tt = 0; tt < 64; tt++) {
        float p = s[tt];
#pragma unroll
        for (int d = 0; d < 32; d++) o[d] += p * Vs[tt * 32 + d];
    }
    const float inv = 1.f / sum;
    float* dst = g_xo + (size_t)w * 32768 + t * 512 + h * 32;
#pragma unroll
    for (int d4 = 0; d4 < 8; d4++) {
        ((float4*)dst)[d4] = make_float4(o[d4*4]*inv, o[d4*4+1]*inv,
                                         o[d4*4+2]*inv, o[d4*4+3]*inv);
    }
}

// ---------------------------------------------------------------------------
// 4) Proj GEMM + bias + window merge: out[b, (wh*8+p)*64 + ww*8+q, c]
// ---------------------------------------------------------------------------
__global__ __launch_bounds__(256) void proj_gemm_kernel(const float* __restrict__ Wmat,
                                                        const float* __restrict__ bias,
                                                        float* __restrict__ out) {
    __shared__ float As[BK][BM];
    __shared__ float Bs[BK][BN];
    const int tid = threadIdx.x;
    const int m0 = blockIdx.x * BM;
    const int n0 = blockIdx.y * BN;
    const int tx = tid & 15;
    const int ty = tid >> 4;

    float acc[8][4];
#pragma unroll
    for (int i = 0; i < 8; i++)
#pragma unroll
        for (int j = 0; j < 4; j++) acc[i][j] = 0.f;

    const int la0 = tid * 2;
    const int bn  = tid >> 2;
    const int bk  = (tid & 3) * 4;

    for (int kb = 0; kb < 512; kb += BK) {
#pragma unroll
        for (int v = 0; v < 2; v++) {
            int la = la0 + v;
            int m  = la >> 2;
            int kq = (la & 3) * 4;
            float4 av = *(const float4*)(g_xo + (size_t)(m0 + m) * 512 + kb + kq);
            As[kq+0][m] = av.x; As[kq+1][m] = av.y;
            As[kq+2][m] = av.z; As[kq+3][m] = av.w;
        }
        {
            float4 bv = *(const float4*)(Wmat + (size_t)(n0 + bn) * 512 + kb + bk);
            Bs[bk+0][bn] = bv.x; Bs[bk+1][bn] = bv.y;
            Bs[bk+2][bn] = bv.z; Bs[bk+3][bn] = bv.w;
        }
        __syncthreads();
#pragma unroll
        for (int k = 0; k < BK; k++) {
            float a[8], b[4];
            float4 a0 = *(const float4*)&As[k][ty * 8];
            float4 a1 = *(const float4*)&As[k][ty * 8 + 4];
            a[0]=a0.x; a[1]=a0.y; a[2]=a0.z; a[3]=a0.w;
            a[4]=a1.x; a[5]=a1.y; a[6]=a1.z; a[7]=a1.w;
            float4 b0 = *(const float4*)&Bs[k][tx * 4];
            b[0]=b0.x; b[1]=b0.y; b[2]=b0.z; b[3]=b0.w;
#pragma unroll
            for (int i = 0; i < 8; i++)
#pragma unroll
                for (int j = 0; j < 4; j++) acc[i][j] += a[i] * b[j];
        }
        __syncthreads();
    }

    const int c = n0 + tx * 4;
    float4 bi = *(const float4*)(bias + c);
#pragma unroll
    for (int i = 0; i < 8; i++) {
        int m = m0 + ty * 8 + i;
        int w = m >> 6, t = m & 63;
        int b  = w >> 6;
        int wh = (w >> 3) & 7;
        int ww = w & 7;
        int p = t >> 3, q = t & 7;
        int npos = (wh * 8 + p) * 64 + (ww * 8 + q);
        float4 o = make_float4(acc[i][0] + bi.x, acc[i][1] + bi.y,
                               acc[i][2] + bi.z, acc[i][3] + bi.w);
        *(float4*)(out + ((size_t)(b * 4096 + npos)) * 512 + c) = o;
    }
}

// ---------------------------------------------------------------------------
extern "C" void kernel_launch(void* const* d_in, const int* in_sizes, int n_in,
                              void* d_out, int out_size) {
    const float* x      = (const float*)d_in[0];
    const float* w_qkv  = (const float*)d_in[1];
    const float* w_proj = (const float*)d_in[2];
    const float* b_proj = (const float*)d_in[3];
    float* out = (float*)d_out;

    gather_kernel<<<16384, 256>>>(x);                       // NWIN*64*64 / 256
    qkv_gemm_kernel<<<dim3(512, 24), 256>>>(w_qkv);         // 65536/128 x 1536/64
    attn_kernel<<<16384, 64>>>();                           // NWIN * NHEAD
    proj_gemm_kernel<<<dim3(512, 8), 256>>>(w_proj, b_proj, out);
}

// round 8
// speedup vs baseline: 2.4653x; 2.4653x over previous
#include <cuda_runtime.h>
#include <cuda_bf16.h>
#include <cstdint>

// Problem constants
#define NWIN   1024           // 16 batches * 8 * 8 windows
#define MTOT   65536          // NWIN * 64 tokens
#define CDIM   512
#define QKVN   1536

// Scratch (device globals — no allocation allowed)
__device__ __nv_bfloat16 g_xw_hi[(size_t)MTOT * CDIM];
__device__ __nv_bfloat16 g_xw_lo[(size_t)MTOT * CDIM];
__device__ float         g_qkv  [(size_t)3 * MTOT * CDIM];   // [s][w][h][t][d]
__device__ __nv_bfloat16 g_xo_hi[(size_t)MTOT * CDIM];
__device__ __nv_bfloat16 g_xo_lo[(size_t)MTOT * CDIM];
__device__ __nv_bfloat16 g_wq_hi[(size_t)QKVN * CDIM];
__device__ __nv_bfloat16 g_wq_lo[(size_t)QKVN * CDIM];
__device__ __nv_bfloat16 g_wp_hi[(size_t)CDIM * CDIM];
__device__ __nv_bfloat16 g_wp_lo[(size_t)CDIM * CDIM];

// ---------------------------------------------------------------------------
// helpers (all plain sm_80-era PTX — valid on compute_103 base target)
// ---------------------------------------------------------------------------
__device__ __forceinline__ uint32_t smem_u32(const void* p) {
    uint32_t a;
    asm("{ .reg .u64 t; cvta.to.shared.u64 t, %1; cvt.u32.u64 %0, t; }" : "=r"(a) : "l"(p));
    return a;
}
__device__ __forceinline__ void cp16(uint32_t s, const void* g) {
    asm volatile("cp.async.cg.shared.global [%0], [%1], 16;" :: "r"(s), "l"(g));
}
__device__ __forceinline__ void ldm_x4(uint32_t* r, uint32_t addr) {
    asm volatile("ldmatrix.sync.aligned.m8n8.x4.shared.b16 {%0,%1,%2,%3}, [%4];"
                 : "=r"(r[0]), "=r"(r[1]), "=r"(r[2]), "=r"(r[3]) : "r"(addr));
}
__device__ __forceinline__ void mma16816(float* c, const uint32_t* a, const uint32_t* b) {
    asm volatile(
        "mma.sync.aligned.m16n8k16.row.col.f32.bf16.bf16.f32 "
        "{%0,%1,%2,%3}, {%4,%5,%6,%7}, {%8,%9}, {%0,%1,%2,%3};"
        : "+f"(c[0]), "+f"(c[1]), "+f"(c[2]), "+f"(c[3])
        : "r"(a[0]), "r"(a[1]), "r"(a[2]), "r"(a[3]), "r"(b[0]), "r"(b[1]));
}

// ---------------------------------------------------------------------------
// 1) Gather + bf16 split: xw[w, t, cc] = x[b, n(i,j), c]
//    c = (t&7)*64 + (t>>3)*8 + cc/64 ; i = (cc>>3)&7 ; j = cc&7
// ---------------------------------------------------------------------------
__global__ __launch_bounds__(256) void gather_split_kernel(const float* __restrict__ x) {
    int idx = blockIdx.x * blockDim.x + threadIdx.x;      // [0, NWIN*64*64)
    int cc64 = idx & 63;
    int t    = (idx >> 6) & 63;
    int w    = idx >> 12;
    int b  = w >> 6;
    int wh = (w >> 3) & 7;
    int ww = w & 7;
    int i = cc64 >> 3;
    int j = cc64 & 7;
    int base_c = (t & 7) * 64 + (t >> 3) * 8;
    int n = (wh * 8 + i) * 64 + (ww * 8 + j);
    const float* src = x + ((size_t)(b * 4096 + n)) * 512 + base_c;
    float4 v0 = *(const float4*)(src);
    float4 v1 = *(const float4*)(src + 4);
    float vv[8] = {v0.x, v0.y, v0.z, v0.w, v1.x, v1.y, v1.z, v1.w};
    size_t off = (size_t)w * 32768 + t * 512 + cc64;
#pragma unroll
    for (int r = 0; r < 8; r++) {
        float v = vv[r];
        __nv_bfloat16 h = __float2bfloat16(v);
        g_xw_hi[off + 64 * r] = h;
        g_xw_lo[off + 64 * r] = __float2bfloat16(v - __bfloat162float(h));
    }
}

// ---------------------------------------------------------------------------
// 1b) Weight split (w_qkv 1536x512, w_proj 512x512)
// ---------------------------------------------------------------------------
__global__ __launch_bounds__(256) void wsplit_kernel(const float* __restrict__ wq,
                                                     const float* __restrict__ wp) {
    int i = blockIdx.x * blockDim.x + threadIdx.x;
    if (i < QKVN * CDIM) {
        float v = wq[i];
        __nv_bfloat16 h = __float2bfloat16(v);
        g_wq_hi[i] = h;
        g_wq_lo[i] = __float2bfloat16(v - __bfloat162float(h));
    } else {
        int k = i - QKVN * CDIM;
        float v = wp[k];
        __nv_bfloat16 h = __float2bfloat16(v);
        g_wp_hi[k] = h;
        g_wp_lo[k] = __float2bfloat16(v - __bfloat162float(h));
    }
}

// ---------------------------------------------------------------------------
// 2) bf16x3 HMMA GEMM: D[m,n] = sum_k A[m,k]*B[n,k], 3 hi/lo passes summed in
//    fp32 register accumulators (err ~2^-16 relative — well under 1e-3).
//    CTA tile 128x128, 8 warps (2x4), warp tile 64x32, K-chunk 64 (128B rows,
//    XOR-16B swizzle -> conflict-free ldmatrix). 3-stage cp.async pipeline.
//    mode 0: A=g_xw, B=g_wq, epilogue scatter to g_qkv[s][w][h][t][d]
//    mode 1: A=g_xo, B=g_wp, epilogue bias + window-merge to out
// ---------------------------------------------------------------------------
#define STG   32768                  // A(16KB) + B(16KB) per stage
#define GSMEM (3 * STG + 1024)
#define NITER 24                     // 3 passes * 8 k-chunks

extern "C" __global__ __launch_bounds__(256, 2)
void gemm3_kernel(const float* __restrict__ bias, float* __restrict__ outp, int mode) {
    extern __shared__ char smem[];
    const int tid  = threadIdx.x;
    const int lane = tid & 31;
    const int wid  = tid >> 5;
    const int wm   = wid & 1;            // 2 warp rows   (64 m each)
    const int wn   = wid >> 1;           // 4 warp cols   (32 n each)
    const int m0 = blockIdx.x * 128;
    const int n0 = blockIdx.y * 128;

    const __nv_bfloat16* Ahi = (mode == 0) ? g_xw_hi : g_xo_hi;
    const __nv_bfloat16* Alo = (mode == 0) ? g_xw_lo : g_xo_lo;
    const __nv_bfloat16* Bhi = (mode == 0) ? g_wq_hi : g_wp_hi;
    const __nv_bfloat16* Blo = (mode == 0) ? g_wq_lo : g_wp_lo;

    uint32_t sbase = smem_u32(smem);
    uint32_t tile0 = (sbase + 1023) & ~1023u;

    float acc[4][4][4];
#pragma unroll
    for (int a = 0; a < 4; a++)
#pragma unroll
        for (int b = 0; b < 4; b++)
#pragma unroll
            for (int c = 0; c < 4; c++) acc[a][b][c] = 0.f;

    // ---- stage loader: one K-chunk (64) of A(128 rows) + B(128 rows) ----
    auto load_stage = [&](int st, int it) {
        int pass = it >> 3;                  // 0: hi*hi, 1: lo*hi, 2: hi*lo
        int kb   = (it & 7) << 6;
        const __nv_bfloat16* Ap = (pass == 1) ? Alo : Ahi;
        const __nv_bfloat16* Bp = (pass == 2) ? Blo : Bhi;
        uint32_t sa = tile0 + st * STG;
        uint32_t sb = sa + 16384;
#pragma unroll
        for (int v = 0; v < 4; v++) {
            int c = tid + v * 256;           // 0..1023
            int r = c >> 3, g = c & 7;
            uint32_t so = r * 128 + ((g ^ (r & 7)) << 4);
            cp16(sa + so, Ap + (size_t)(m0 + r) * 512 + kb + g * 8);
            cp16(sb + so, Bp + (size_t)(n0 + r) * 512 + kb + g * 8);
        }
        asm volatile("cp.async.commit_group;" ::: "memory");
    };

    load_stage(0, 0);
    load_stage(1, 1);

    const int la = lane & 15;                // ldmatrix row within 16
    const int hi = lane >> 4;                // 0: k-lo 16B, 1: k-hi 16B

    for (int it = 0; it < NITER; ++it) {
        asm volatile("cp.async.wait_group 1;" ::: "memory");
        __syncthreads();
        if (it + 2 < NITER) load_stage((it + 2) % 3, it + 2);
        else asm volatile("cp.async.commit_group;" ::: "memory");   // keep group count aligned

        uint32_t sa = tile0 + (it % 3) * STG;
        uint32_t sb = sa + 16384;
#pragma unroll
        for (int s = 0; s < 4; s++) {        // 4 x k16 within the 64-chunk
            uint32_t af[4][4];
#pragma unroll
            for (int mt = 0; mt < 4; mt++) {
                int r  = wm * 64 + mt * 16 + la;
                int ch = 2 * s + hi;
                ldm_x4(af[mt], sa + r * 128 + ((ch ^ (r & 7)) << 4));
            }
            uint32_t bf[4][2];
#pragma unroll
            for (int nh = 0; nh < 2; nh++) {
                int r  = wn * 32 + nh * 16 + la;
                int ch = 2 * s + hi;
                uint32_t t4[4];
                ldm_x4(t4, sb + r * 128 + ((ch ^ (r & 7)) << 4));
                bf[nh * 2 + 0][0] = t4[0]; bf[nh * 2 + 0][1] = t4[2];
                bf[nh * 2 + 1][0] = t4[1]; bf[nh * 2 + 1][1] = t4[3];
            }
#pragma unroll
            for (int mt = 0; mt < 4; mt++)
#pragma unroll
                for (int nt = 0; nt < 4; nt++)
                    mma16816(acc[mt][nt], af[mt], bf[nt]);
        }
        __syncthreads();
    }

    // ---- epilogue straight from C fragments ----
    const int row0 = lane >> 2;              // 0..7
    const int col0 = (lane & 3) * 2;         // 0,2,4,6
#pragma unroll
    for (int mt = 0; mt < 4; mt++) {
#pragma unroll
        for (int half = 0; half < 2; half++) {
            int m = m0 + wm * 64 + mt * 16 + row0 + half * 8;
            int w = m >> 6, tt = m & 63;
#pragma unroll
            for (int nt = 0; nt < 4; nt++) {
                int n = n0 + wn * 32 + nt * 8 + col0;
                float v0 = acc[mt][nt][half * 2 + 0];
                float v1 = acc[mt][nt][half * 2 + 1];
                if (mode == 0) {
                    int s = n >> 9, h = (n >> 5) & 15, d = n & 31;
                    float* dst = g_qkv + (((size_t)s * NWIN + w) * 16 + h) * 2048
                               + (size_t)tt * 32 + d;
                    *(float2*)dst = make_float2(v0, v1);
                } else {
                    int b  = w >> 6;
                    int wh = (w >> 3) & 7;
                    int ww = w & 7;
                    int p = tt >> 3, q = tt & 7;
                    int npos = (wh * 8 + p) * 64 + (ww * 8 + q);
                    float2 bi = *(const float2*)(bias + n);
                    float* dst = outp + ((size_t)(b * 4096 + npos)) * 512 + n;
                    *(float2*)dst = make_float2(v0 + bi.x, v1 + bi.y);
                }
            }
        }
    }
}

// ---------------------------------------------------------------------------
// 3) Attention: one block per (window, head); 64 threads (one per query row).
//    Epilogue emits bf16 hi/lo for the proj GEMM.
// ---------------------------------------------------------------------------
__global__ __launch_bounds__(64) void attn_kernel() {
    __shared__ float Qs[64 * 33];
    __shared__ float Ks[64 * 32];
    __shared__ float Vs[64 * 32];
    const int w = blockIdx.x >> 4;
    const int h = blockIdx.x & 15;
    const size_t base = ((size_t)w * 16 + h) * 2048;
    const float* qb = g_qkv + base;
    const float* kb = g_qkv + (size_t)MTOT * 512 + base;
    const float* vb = g_qkv + (size_t)2 * MTOT * 512 + base;
    const int t = threadIdx.x;

#pragma unroll
    for (int v = 0; v < 8; v++) {
        int idx = v * 64 + t;
        ((float4*)Ks)[idx] = ((const float4*)kb)[idx];
        ((float4*)Vs)[idx] = ((const float4*)vb)[idx];
        float4 qv = ((const float4*)qb)[idx];
        int row = idx >> 3;
        int d0  = (idx & 7) * 4;
        Qs[row * 33 + d0 + 0] = qv.x;
        Qs[row * 33 + d0 + 1] = qv.y;
        Qs[row * 33 + d0 + 2] = qv.z;
        Qs[row * 33 + d0 + 3] = qv.w;
    }
    __syncthreads();

    const float* qrow = Qs + t * 33;
    float s[64];
    float mx = -1e30f;
#pragma unroll
    for (int tt = 0; tt < 64; tt++) {
        float dot = 0.f;
#pragma unroll
        for (int d = 0; d < 32; d++) dot += qrow[d] * Ks[tt * 32 + d];
        dot *= 0.17677669529663687f;
        s[tt] = dot;
        mx = fmaxf(mx, dot);
    }
    float sum = 0.f;
#pragma unroll
    for (int tt = 0; tt < 64; tt++) {
        float e = __expf(s[tt] - mx);
        s[tt] = e;
        sum += e;
    }
    float o[32];
#pragma unroll
    for (int d = 0; d < 32; d++) o[d] = 0.f;
#pragma unroll
    for (int tt = 0; tt < 64; tt++) {
        float p = s[tt];
#pragma unroll
        for (int d = 0; d < 32; d++) o[d] += p * Vs[tt * 32 + d];
    }
    const float inv = 1.f / sum;
    size_t ob = ((size_t)w * 64 + t) * 512 + h * 32;
#pragma unroll
    for (int d0 = 0; d0 < 32; d0 += 8) {
        __nv_bfloat16 hb[8], lb[8];
#pragma unroll
        for (int jj = 0; jj < 8; jj++) {
            float v = o[d0 + jj] * inv;
            __nv_bfloat16 hh = __float2bfloat16(v);
            hb[jj] = hh;
            lb[jj] = __float2bfloat16(v - __bfloat162float(hh));
        }
        *(uint4*)(g_xo_hi + ob + d0) = *(uint4*)hb;
        *(uint4*)(g_xo_lo + ob + d0) = *(uint4*)lb;
    }
}

// ---------------------------------------------------------------------------
extern "C" void kernel_launch(void* const* d_in, const int* in_sizes, int n_in,
                              void* d_out, int out_size) {
    const float* x      = (const float*)d_in[0];
    const float* w_qkv  = (const float*)d_in[1];
    const float* w_proj = (const float*)d_in[2];
    const float* b_proj = (const float*)d_in[3];
    float* out = (float*)d_out;

    cudaFuncSetAttribute(gemm3_kernel, cudaFuncAttributeMaxDynamicSharedMemorySize, GSMEM);

    gather_split_kernel<<<16384, 256>>>(x);
    wsplit_kernel<<<4096, 256>>>(w_qkv, w_proj);
    gemm3_kernel<<<dim3(512, 12), 256, GSMEM>>>(nullptr, nullptr, 0);  // QKV
    attn_kernel<<<16384, 64>>>();
    gemm3_kernel<<<dim3(512, 4), 256, GSMEM>>>(b_proj, out, 1);        // proj
}